// round 11
// baseline (speedup 1.0000x reference)
#include <cuda_runtime.h>
#include <cuda_fp16.h>
#include <math.h>

#define NN 100000
#define NE 1600000
#define SCAN_CHUNK 1024
#define NCHUNK ((NN + SCAN_CHUNK - 1) / SCAN_CHUNK)   // 98
#define CSR_CAP (NE + 4 * NN)                          // padded CSR capacity (2.0M)

// ---------------- scratch (allocation-free) ----------------
// Row NN of each GATHER buffer is the sentinel zero row: device globals are
// zero-initialized and no kernel ever writes that row AT ITS OWN WIDTH.
// g_yA/g_yB are 16-wide message buffers; g_yC is the DEDICATED 8-wide buffer
// (layer 3) — reusing a 16-wide buffer at width 8 would put stale data at its
// 8-wide row NN (the R10 bug).
__device__ __align__(128) __half g_yA[(NN + 1) * 16];
__device__ __align__(128) __half g_yB[(NN + 1) * 16];
__device__ __align__(128) __half g_yC[(NN + 1) * 8];
__device__ __align__(128) float  g_zA[NN * 16];
__device__ __align__(128) float  g_zB[NN * 16];
__device__ int g_cnt[NN];                        // true in-degree
__device__ int g_off[NN + 1];                    // padded (4-aligned) row offsets
__device__ int g_cur[NN];                        // placement cursors
__device__ __align__(16) int g_csr[CSR_CAP];     // padded CSR src indices
__device__ unsigned long long g_state[NCHUNK];   // lookback: (flag<<32)|sum

__device__ __forceinline__ float elu_f(float v) {
    return v > 0.0f ? v : expm1f(v);
}

// ---------------------------------------------------------------------------
// CSR build: memset -> hist(int4, RED) -> scan(padded) -> fill(sentinel) -> place
// ---------------------------------------------------------------------------
__global__ void __launch_bounds__(256) hist_kernel(
    const int* __restrict__ dst, int* __restrict__ cnt)
{
    int e4 = blockIdx.x * blockDim.x + threadIdx.x;
    if (e4 >= NE / 4) return;
    int4 d = reinterpret_cast<const int4*>(dst)[e4];
    atomicAdd(cnt + d.x, 1);   // RED (no return)
    atomicAdd(cnt + d.y, 1);
    atomicAdd(cnt + d.z, 1);
    atomicAdd(cnt + d.w, 1);
}

// Fill padded CSR with sentinel NN (runs on side stream, hidden).
__global__ void __launch_bounds__(256) fill_csr_kernel(int* __restrict__ csr) {
    int i = blockIdx.x * blockDim.x + threadIdx.x;
    int4 v = make_int4(NN, NN, NN, NN);
    if (i < CSR_CAP / 4) reinterpret_cast<int4*>(csr)[i] = v;
}

// One launch: per-block scan of alignUp(cnt,4) + decoupled lookback (98 blocks
// all co-resident on 148 SMs -> spin-wait deadlock-free).
__global__ void __launch_bounds__(256) scan_onepass_kernel(
    const int* __restrict__ cnt, int* __restrict__ off, int* __restrict__ cur)
{
    __shared__ int wsum[8];
    __shared__ int s_base;
    int b = blockIdx.x, t = threadIdx.x;
    int gbase = b * SCAN_CHUNK + t * 4;
    int v0 = (gbase + 0 < NN) ? ((cnt[gbase + 0] + 3) & ~3) : 0;
    int v1 = (gbase + 1 < NN) ? ((cnt[gbase + 1] + 3) & ~3) : 0;
    int v2 = (gbase + 2 < NN) ? ((cnt[gbase + 2] + 3) & ~3) : 0;
    int v3 = (gbase + 3 < NN) ? ((cnt[gbase + 3] + 3) & ~3) : 0;
    int s = v0 + v1 + v2 + v3;

    int lane = t & 31, wid = t >> 5;
    int sc = s;
#pragma unroll
    for (int o = 1; o < 32; o <<= 1) {
        int n = __shfl_up_sync(0xffffffff, sc, o);
        if (lane >= o) sc += n;
    }
    if (lane == 31) wsum[wid] = sc;
    __syncthreads();
    if (wid == 0) {
        int ws = (lane < 8) ? wsum[lane] : 0;
#pragma unroll
        for (int o = 1; o < 8; o <<= 1) {
            int n = __shfl_up_sync(0xffffffff, ws, o);
            if (lane >= o) ws += n;
        }
        if (lane < 8) wsum[lane] = ws;
    }
    __syncthreads();
    int total = wsum[7];

    if (b == 0) {
        if (t == 0) {
            atomicExch(&g_state[0], (2ULL << 32) | (unsigned long long)(unsigned)total);
            s_base = 0;
        }
    } else {
        if (t == 0)
            atomicExch(&g_state[b], (1ULL << 32) | (unsigned long long)(unsigned)total);
        if (wid == 0) {
            int sum = 0;
            int base_j = b - 1;
            while (true) {
                int j = base_j - lane;
                int flag, val;
                if (j >= 0) {
                    unsigned long long v;
                    do { v = *(volatile unsigned long long*)&g_state[j]; }
                    while ((unsigned)(v >> 32) == 0u);
                    flag = (int)(v >> 32);
                    val = (int)(unsigned)v;
                } else { flag = 2; val = 0; }
                unsigned m = __ballot_sync(0xffffffffu, flag == 2);
                int firstDone = (m == 0u) ? -1 : (__ffs(m) - 1);
                int contrib = (firstDone < 0 || lane <= firstDone) ? val : 0;
#pragma unroll
                for (int o = 16; o >= 1; o >>= 1)
                    contrib += __shfl_xor_sync(0xffffffffu, contrib, o);
                sum += contrib;
                if (firstDone >= 0) break;
                base_j -= 32;
            }
            if (lane == 0) {
                atomicExch(&g_state[b],
                           (2ULL << 32) | (unsigned long long)(unsigned)(sum + total));
                s_base = sum;
            }
        }
    }
    __syncthreads();

    int excl = sc - s + (wid > 0 ? wsum[wid - 1] : 0) + s_base;
    if (gbase + 0 < NN) { off[gbase + 0] = excl; cur[gbase + 0] = excl; } excl += v0;
    if (gbase + 1 < NN) { off[gbase + 1] = excl; cur[gbase + 1] = excl; } excl += v1;
    if (gbase + 2 < NN) { off[gbase + 2] = excl; cur[gbase + 2] = excl; } excl += v2;
    if (gbase + 3 < NN) { off[gbase + 3] = excl; cur[gbase + 3] = excl; }
}

__global__ void place_kernel(const int* __restrict__ src, const int* __restrict__ dst,
                             int* __restrict__ cur, int* __restrict__ csr) {
    int e = blockIdx.x * blockDim.x + threadIdx.x;
    if (e >= NE) return;
    int d = __ldg(dst + e);
    int p = atomicAdd(cur + d, 1);
    csr[p] = __ldg(src + e);
}

// ---------------------------------------------------------------------------
// Transform (layer 1): gridDim.y: 0 -> y(half) = x@Wl^T ; 1 -> z(f32) = x@Wr^T + b
// ---------------------------------------------------------------------------
template <int IN, int OUT>
__global__ void __launch_bounds__(256) transform2_kernel(
    const float* __restrict__ x, const float* __restrict__ Wl,
    const float* __restrict__ Wr, const float* __restrict__ bias,
    __half* __restrict__ y, float* __restrict__ z)
{
    __shared__ __align__(16) float sW[IN * OUT];   // [k][o]
    __shared__ float sb[OUT];
    const bool zpass = (blockIdx.y == 1);
    const float* W = zpass ? Wr : Wl;
    for (int i = threadIdx.x; i < IN * OUT; i += 256) {
        int o = i / IN, k = i - o * IN;
        sW[k * OUT + o] = W[i];
    }
    if (threadIdx.x < OUT) sb[threadIdx.x] = zpass ? bias[threadIdx.x] : 0.0f;
    __syncthreads();

    int node = blockIdx.x * 256 + threadIdx.x;
    if (node >= NN) return;

    float acc[OUT];
#pragma unroll
    for (int o = 0; o < OUT; o++) acc[o] = sb[o];

    const float4* xr = reinterpret_cast<const float4*>(x + (size_t)node * IN);
#pragma unroll
    for (int k4 = 0; k4 < IN / 4; k4++) {
        float4 xv = xr[k4];
#pragma unroll
        for (int o = 0; o < OUT; o++) {
            acc[o] = fmaf(xv.x, sW[(4 * k4 + 0) * OUT + o], acc[o]);
            acc[o] = fmaf(xv.y, sW[(4 * k4 + 1) * OUT + o], acc[o]);
            acc[o] = fmaf(xv.z, sW[(4 * k4 + 2) * OUT + o], acc[o]);
            acc[o] = fmaf(xv.w, sW[(4 * k4 + 3) * OUT + o], acc[o]);
        }
    }

    if (zpass) {
        float4* zrow = reinterpret_cast<float4*>(z + (size_t)node * OUT);
#pragma unroll
        for (int j = 0; j < OUT / 4; j++)
            zrow[j] = make_float4(acc[4 * j], acc[4 * j + 1], acc[4 * j + 2], acc[4 * j + 3]);
    } else {
        __half2* yrow = reinterpret_cast<__half2*>(y + (size_t)node * OUT);
#pragma unroll
        for (int j = 0; j < OUT / 2; j++)
            yrow[j] = __floats2half2_rn(acc[2 * j], acc[2 * j + 1]);
    }
}

// ---------------------------------------------------------------------------
// Branch-free padded gather: int4 index loads, 1-ahead pipeline, fp32 acc.
// Segment start is 4-aligned and length is a multiple of 4 by construction;
// padding indices are NN -> gather zero row.
// ---------------------------------------------------------------------------
template <int W>
__device__ __forceinline__ float gather4(const __half* __restrict__ y,
                                         int4 a, int lane)
{
    float v0 = __half2float(__ldg(y + (size_t)a.x * W + lane));
    float v1 = __half2float(__ldg(y + (size_t)a.y * W + lane));
    float v2 = __half2float(__ldg(y + (size_t)a.z * W + lane));
    float v3 = __half2float(__ldg(y + (size_t)a.w * W + lane));
    return (v0 + v1) + (v2 + v3);
}

template <int W>
__device__ __forceinline__ float gather_mean_p(
    const int* __restrict__ csr, const __half* __restrict__ y,
    int beg, int cnt, int lane)
{
    int n4 = (cnt + 3) >> 2;
    const int4* ip = reinterpret_cast<const int4*>(csr + beg);
    float acc = 0.0f;
    if (n4 > 0) {
        int4 a = __ldg(ip);
        for (int j = 1; j < n4; j++) {
            int4 b = __ldg(ip + j);
            acc += gather4<W>(y, a, lane);
            a = b;
        }
        acc += gather4<W>(y, a, lane);
    }
    return acc / fmaxf((float)cnt, 1.0f);
}

// ---------------------------------------------------------------------------
// Fused aggregate + ELU + NEXT-layer transform (shfl broadcast of h-row).
// ---------------------------------------------------------------------------
template <int OUT_NEXT>
__global__ void __launch_bounds__(256) agg_xform_kernel(
    const int* __restrict__ off, const int* __restrict__ cnt,
    const int* __restrict__ csr,
    const __half* __restrict__ y, const float* __restrict__ z,
    const float* __restrict__ Wl, const float* __restrict__ Wr,
    const float* __restrict__ bias,
    __half* __restrict__ yn, float* __restrict__ zn)
{
    __shared__ float sWl[16 * OUT_NEXT];   // [k][o]
    __shared__ float sWr[16 * OUT_NEXT];
    __shared__ float sb[OUT_NEXT];
    for (int i = threadIdx.x; i < 16 * OUT_NEXT; i += 256) {
        int o = i / 16, k = i - o * 16;
        sWl[k * OUT_NEXT + o] = Wl[i];
        sWr[k * OUT_NEXT + o] = Wr[i];
    }
    if (threadIdx.x < OUT_NEXT) sb[threadIdx.x] = bias[threadIdx.x];
    __syncthreads();

    int lane = threadIdx.x & 15;
    int node = (blockIdx.x * 256 + threadIdx.x) >> 4;   // grid exact

    int beg = __ldg(off + node);
    int deg = __ldg(cnt + node);

    float mean = gather_mean_p<16>(csr, y, beg, deg, lane);
    float v = elu_f(mean + __ldg(z + (size_t)node * 16 + lane));

    float accY = 0.0f;
    float accZ = (lane < OUT_NEXT) ? sb[lane] : 0.0f;
#pragma unroll
    for (int k = 0; k < 16; k++) {
        float hk = __shfl_sync(0xffffffffu, v, k, 16);
        if (lane < OUT_NEXT) {
            accY = fmaf(hk, sWl[k * OUT_NEXT + lane], accY);
            accZ = fmaf(hk, sWr[k * OUT_NEXT + lane], accZ);
        }
    }
    if (lane < OUT_NEXT) {
        yn[(size_t)node * OUT_NEXT + lane] = __float2half_rn(accY);
        zn[(size_t)node * OUT_NEXT + lane] = accZ;
    }
}

// ---------------------------------------------------------------------------
// Final aggregate (width 8) + ELU + log_softmax.
// ---------------------------------------------------------------------------
__global__ void __launch_bounds__(256) agg_final_kernel(
    const int* __restrict__ off, const int* __restrict__ cnt,
    const int* __restrict__ csr,
    const __half* __restrict__ y, const float* __restrict__ z,
    float* __restrict__ out)
{
    int lane = threadIdx.x & 7;
    int node = (blockIdx.x * 256 + threadIdx.x) >> 3;   // grid exact

    int beg = __ldg(off + node);
    int deg = __ldg(cnt + node);

    float mean = gather_mean_p<8>(csr, y, beg, deg, lane);
    float v = elu_f(mean + __ldg(z + (size_t)node * 8 + lane));

    float m = v;
#pragma unroll
    for (int o = 4; o >= 1; o >>= 1)
        m = fmaxf(m, __shfl_xor_sync(0xffffffff, m, o, 8));
    float ex = expf(v - m);
    float s = ex;
#pragma unroll
    for (int o = 4; o >= 1; o >>= 1)
        s += __shfl_xor_sync(0xffffffff, s, o, 8);
    v = v - m - logf(s);

    out[(size_t)node * 8 + lane] = v;
}

// ---------------------------------------------------------------------------
extern "C" void kernel_launch(void* const* d_in, const int* in_sizes, int n_in,
                              void* d_out, int out_size)
{
    (void)in_sizes; (void)n_in; (void)out_size;

    const float* x   = (const float*)d_in[0];
    const int*   ei  = (const int*)d_in[1];   // int32 (JAX x64-disabled)
    const float* W1l = (const float*)d_in[2];
    const float* W1r = (const float*)d_in[3];
    const float* b1  = (const float*)d_in[4];
    const float* W2l = (const float*)d_in[5];
    const float* W2r = (const float*)d_in[6];
    const float* b2  = (const float*)d_in[7];
    const float* W3l = (const float*)d_in[8];
    const float* W3r = (const float*)d_in[9];
    const float* b3  = (const float*)d_in[10];
    float* out = (float*)d_out;

    const int* src = ei;
    const int* dst = ei + NE;

    __half *pyA, *pyB, *pyC;
    float *pzA, *pzB;
    int *pcnt, *poff, *pcur, *pcsr;
    unsigned long long* pstate;
    cudaGetSymbolAddress((void**)&pyA,    g_yA);
    cudaGetSymbolAddress((void**)&pyB,    g_yB);
    cudaGetSymbolAddress((void**)&pyC,    g_yC);
    cudaGetSymbolAddress((void**)&pzA,    g_zA);
    cudaGetSymbolAddress((void**)&pzB,    g_zB);
    cudaGetSymbolAddress((void**)&pcnt,   g_cnt);
    cudaGetSymbolAddress((void**)&poff,   g_off);
    cudaGetSymbolAddress((void**)&pcur,   g_cur);
    cudaGetSymbolAddress((void**)&pcsr,   g_csr);
    cudaGetSymbolAddress((void**)&pstate, g_state);

    const int nbN = (NN + 255) / 256;
    const int nbE = (NE + 255) / 256;
    const int nbE4 = (NE / 4 + 255) / 256;
    const int nbFill = (CSR_CAP / 4 + 255) / 256;

    // Side stream: csr sentinel fill (needed by place) then transform1
    // (needed by agg1). Both independent of hist/scan.
    cudaStream_t s2;
    cudaStreamCreateWithFlags(&s2, cudaStreamNonBlocking);
    cudaEvent_t evFork, evFill, evT1;
    cudaEventCreateWithFlags(&evFork, cudaEventDisableTiming);
    cudaEventCreateWithFlags(&evFill, cudaEventDisableTiming);
    cudaEventCreateWithFlags(&evT1,   cudaEventDisableTiming);

    cudaEventRecord(evFork, 0);
    cudaStreamWaitEvent(s2, evFork, 0);
    fill_csr_kernel<<<nbFill, 256, 0, s2>>>(pcsr);
    cudaEventRecord(evFill, s2);
    transform2_kernel<48, 16><<<dim3(nbN, 2), 256, 0, s2>>>(x, W1l, W1r, b1, pyA, pzA);
    cudaEventRecord(evT1, s2);

    // ---- CSR build on the main stream ----
    cudaMemsetAsync(pcnt, 0, NN * sizeof(int));
    cudaMemsetAsync(pstate, 0, NCHUNK * sizeof(unsigned long long));
    hist_kernel<<<nbE4, 256>>>(dst, pcnt);
    scan_onepass_kernel<<<NCHUNK, 256>>>(pcnt, poff, pcur);
    cudaStreamWaitEvent(0, evFill, 0);   // fill must precede place
    place_kernel<<<nbE, 256>>>(src, dst, pcur, pcsr);

    cudaStreamWaitEvent(0, evT1, 0);     // join transform1

    // ---- Layer 1 agg + layer 2 transform: -> yB,zB (16) ----
    agg_xform_kernel<16><<<NN * 16 / 256, 256>>>(poff, pcnt, pcsr, pyA, pzA,
                                                 W2l, W2r, b2, pyB, pzB);
    // ---- Layer 2 agg + layer 3 transform: -> yC (8-wide, dedicated), zA ----
    agg_xform_kernel<8><<<NN * 16 / 256, 256>>>(poff, pcnt, pcsr, pyB, pzB,
                                                W3l, W3r, b3, pyC, pzA);
    // ---- Layer 3 agg + log_softmax ----
    agg_final_kernel<<<NN * 8 / 256, 256>>>(poff, pcnt, pcsr, pyC, pzA, out);
}

// round 12
// speedup vs baseline: 1.1692x; 1.1692x over previous
#include <cuda_runtime.h>
#include <cuda_fp16.h>
#include <math.h>

#define NN 100000
#define NE 1600000
#define SCAN_CHUNK 1024
#define NCHUNK ((NN + SCAN_CHUNK - 1) / SCAN_CHUNK)   // 98

// ---------------- scratch (allocation-free) ----------------
__device__ __align__(128) __half g_yA[NN * 16];   // 16-wide fp16 messages
__device__ __align__(128) __half g_yB[NN * 16];
__device__ __align__(128) __half g_yC[NN * 8];    // 8-wide fp16 messages (layer 3)
__device__ __align__(128) float  g_zA[NN * 16];   // fp32 root terms (16-wide)
__device__ __align__(128) float  g_zB[NN * 16];
__device__ __align__(128) float  g_zC[NN * 8];    // 8-wide root terms
__device__ int g_cnt[NN];                        // in-degree histogram
__device__ int g_off[NN + 1];                    // CSR row offsets
__device__ int g_cur[NN];                        // placement cursors
__device__ int g_csr[NE];                        // CSR src indices (grouped by dst)
__device__ unsigned long long g_state[NCHUNK];   // lookback: (flag<<32)|sum

__device__ __forceinline__ float elu_f(float v) {
    return v > 0.0f ? v : expm1f(v);
}

// ---------------------------------------------------------------------------
// CSR build (R7/R9-proven): memset -> hist(RED) -> single-pass scan -> place
// ---------------------------------------------------------------------------
__global__ void hist_kernel(const int* __restrict__ dst, int* __restrict__ cnt) {
    int e = blockIdx.x * blockDim.x + threadIdx.x;
    if (e < NE) atomicAdd(cnt + __ldg(dst + e), 1);   // RED (no return)
}

__global__ void __launch_bounds__(256) scan_onepass_kernel(
    const int* __restrict__ cnt, int* __restrict__ off, int* __restrict__ cur)
{
    __shared__ int wsum[8];
    __shared__ int s_base;
    int b = blockIdx.x, t = threadIdx.x;
    int gbase = b * SCAN_CHUNK + t * 4;
    int v0 = (gbase + 0 < NN) ? cnt[gbase + 0] : 0;
    int v1 = (gbase + 1 < NN) ? cnt[gbase + 1] : 0;
    int v2 = (gbase + 2 < NN) ? cnt[gbase + 2] : 0;
    int v3 = (gbase + 3 < NN) ? cnt[gbase + 3] : 0;
    int s = v0 + v1 + v2 + v3;

    int lane = t & 31, wid = t >> 5;
    int sc = s;
#pragma unroll
    for (int o = 1; o < 32; o <<= 1) {
        int n = __shfl_up_sync(0xffffffff, sc, o);
        if (lane >= o) sc += n;
    }
    if (lane == 31) wsum[wid] = sc;
    __syncthreads();
    if (wid == 0) {
        int ws = (lane < 8) ? wsum[lane] : 0;
#pragma unroll
        for (int o = 1; o < 8; o <<= 1) {
            int n = __shfl_up_sync(0xffffffff, ws, o);
            if (lane >= o) ws += n;
        }
        if (lane < 8) wsum[lane] = ws;   // inclusive warp sums
    }
    __syncthreads();
    int total = wsum[7];

    if (b == 0) {
        if (t == 0) {
            atomicExch(&g_state[0], (2ULL << 32) | (unsigned long long)(unsigned)total);
            s_base = 0;
        }
    } else {
        if (t == 0)
            atomicExch(&g_state[b], (1ULL << 32) | (unsigned long long)(unsigned)total);
        if (wid == 0) {
            int sum = 0;
            int base_j = b - 1;
            while (true) {
                int j = base_j - lane;
                int flag, val;
                if (j >= 0) {
                    unsigned long long v;
                    do { v = *(volatile unsigned long long*)&g_state[j]; }
                    while ((unsigned)(v >> 32) == 0u);
                    flag = (int)(v >> 32);
                    val = (int)(unsigned)v;
                } else { flag = 2; val = 0; }
                unsigned m = __ballot_sync(0xffffffffu, flag == 2);
                int firstDone = (m == 0u) ? -1 : (__ffs(m) - 1);
                int contrib = (firstDone < 0 || lane <= firstDone) ? val : 0;
#pragma unroll
                for (int o = 16; o >= 1; o >>= 1)
                    contrib += __shfl_xor_sync(0xffffffffu, contrib, o);
                sum += contrib;
                if (firstDone >= 0) break;
                base_j -= 32;
            }
            if (lane == 0) {
                atomicExch(&g_state[b],
                           (2ULL << 32) | (unsigned long long)(unsigned)(sum + total));
                s_base = sum;
            }
        }
    }
    __syncthreads();

    int excl = sc - s + (wid > 0 ? wsum[wid - 1] : 0) + s_base;
    if (gbase + 0 < NN) { off[gbase + 0] = excl; cur[gbase + 0] = excl; } excl += v0;
    if (gbase + 1 < NN) { off[gbase + 1] = excl; cur[gbase + 1] = excl; } excl += v1;
    if (gbase + 2 < NN) { off[gbase + 2] = excl; cur[gbase + 2] = excl; } excl += v2;
    if (gbase + 3 < NN) { off[gbase + 3] = excl; cur[gbase + 3] = excl; }
    if (b == 0 && t == 0) off[NN] = NE;
}

__global__ void place_kernel(const int* __restrict__ src, const int* __restrict__ dst,
                             int* __restrict__ cur, int* __restrict__ csr) {
    int e = blockIdx.x * blockDim.x + threadIdx.x;
    if (e >= NE) return;
    int d = __ldg(dst + e);
    int p = atomicAdd(cur + d, 1);
    csr[p] = __ldg(src + e);
}

// ---------------------------------------------------------------------------
// Transform (layer 1): gridDim.y: 0 -> y(half2 rows) ; 1 -> z(f32) = x@Wr^T + b
// ---------------------------------------------------------------------------
template <int IN, int OUT>
__global__ void __launch_bounds__(256) transform2_kernel(
    const float* __restrict__ x, const float* __restrict__ Wl,
    const float* __restrict__ Wr, const float* __restrict__ bias,
    __half* __restrict__ y, float* __restrict__ z)
{
    __shared__ __align__(16) float sW[IN * OUT];   // [k][o]
    __shared__ float sb[OUT];
    const bool zpass = (blockIdx.y == 1);
    const float* W = zpass ? Wr : Wl;
    for (int i = threadIdx.x; i < IN * OUT; i += 256) {
        int o = i / IN, k = i - o * IN;
        sW[k * OUT + o] = W[i];
    }
    if (threadIdx.x < OUT) sb[threadIdx.x] = zpass ? bias[threadIdx.x] : 0.0f;
    __syncthreads();

    int node = blockIdx.x * 256 + threadIdx.x;
    if (node >= NN) return;

    float acc[OUT];
#pragma unroll
    for (int o = 0; o < OUT; o++) acc[o] = sb[o];

    const float4* xr = reinterpret_cast<const float4*>(x + (size_t)node * IN);
#pragma unroll
    for (int k4 = 0; k4 < IN / 4; k4++) {
        float4 xv = xr[k4];
#pragma unroll
        for (int o = 0; o < OUT; o++) {
            acc[o] = fmaf(xv.x, sW[(4 * k4 + 0) * OUT + o], acc[o]);
            acc[o] = fmaf(xv.y, sW[(4 * k4 + 1) * OUT + o], acc[o]);
            acc[o] = fmaf(xv.z, sW[(4 * k4 + 2) * OUT + o], acc[o]);
            acc[o] = fmaf(xv.w, sW[(4 * k4 + 3) * OUT + o], acc[o]);
        }
    }

    if (zpass) {
        float4* zrow = reinterpret_cast<float4*>(z + (size_t)node * OUT);
#pragma unroll
        for (int j = 0; j < OUT / 4; j++)
            zrow[j] = make_float4(acc[4 * j], acc[4 * j + 1], acc[4 * j + 2], acc[4 * j + 3]);
    } else {
        __half2* yrow = reinterpret_cast<__half2*>(y + (size_t)node * OUT);
#pragma unroll
        for (int j = 0; j < OUT / 2; j++)
            yrow[j] = __floats2half2_rn(acc[2 * j], acc[2 * j + 1]);
    }
}

// ---------------------------------------------------------------------------
// half2 pipelined mean gather: lane owns half2 #lane of an 8-half2 row.
// Per warp: 4 nodes -> 0.5 LDG warp-inst per edge.
// ---------------------------------------------------------------------------
__device__ __forceinline__ float2 gather_mean_h2(
    const int* __restrict__ csr, const __half2* __restrict__ y2,
    int beg, int end, int lane)
{
    float ax = 0.0f, ay = 0.0f;
    int i = beg;
    int a0 = 0, a1 = 0, a2 = 0, a3 = 0;
    bool have = (i + 4 <= end);
    if (have) {
        a0 = __ldg(csr + i + 0);
        a1 = __ldg(csr + i + 1);
        a2 = __ldg(csr + i + 2);
        a3 = __ldg(csr + i + 3);
    }
    for (; i + 8 <= end; i += 4) {
        int b0 = __ldg(csr + i + 4);
        int b1 = __ldg(csr + i + 5);
        int b2 = __ldg(csr + i + 6);
        int b3 = __ldg(csr + i + 7);
        float2 v0 = __half22float2(__ldg(y2 + (size_t)a0 * 8 + lane));
        float2 v1 = __half22float2(__ldg(y2 + (size_t)a1 * 8 + lane));
        float2 v2 = __half22float2(__ldg(y2 + (size_t)a2 * 8 + lane));
        float2 v3 = __half22float2(__ldg(y2 + (size_t)a3 * 8 + lane));
        ax += (v0.x + v1.x) + (v2.x + v3.x);
        ay += (v0.y + v1.y) + (v2.y + v3.y);
        a0 = b0; a1 = b1; a2 = b2; a3 = b3;
    }
    if (have) {
        float2 v0 = __half22float2(__ldg(y2 + (size_t)a0 * 8 + lane));
        float2 v1 = __half22float2(__ldg(y2 + (size_t)a1 * 8 + lane));
        float2 v2 = __half22float2(__ldg(y2 + (size_t)a2 * 8 + lane));
        float2 v3 = __half22float2(__ldg(y2 + (size_t)a3 * 8 + lane));
        ax += (v0.x + v1.x) + (v2.x + v3.x);
        ay += (v0.y + v1.y) + (v2.y + v3.y);
        i += 4;
    }
    for (; i < end; i++) {
        float2 v = __half22float2(__ldg(y2 + (size_t)__ldg(csr + i) * 8 + lane));
        ax += v.x; ay += v.y;
    }
    float inv = 1.0f / fmaxf((float)(end - beg), 1.0f);
    return make_float2(ax * inv, ay * inv);
}

// ---------------------------------------------------------------------------
// Fused aggregate (8 half2-lanes per node) + ELU + NEXT-layer transform.
// Lane owns input features {2l, 2l+1}; for OUT_NEXT=16 it also owns outputs
// {2l, 2l+1}; for OUT_NEXT=8 it owns output l. h-row exchanged via width-8 shfl.
// ---------------------------------------------------------------------------
template <int OUT_NEXT>
__global__ void __launch_bounds__(256) agg_xform_kernel(
    const int* __restrict__ off, const int* __restrict__ csr,
    const __half* __restrict__ y, const float* __restrict__ z,
    const float* __restrict__ Wl, const float* __restrict__ Wr,
    const float* __restrict__ bias,
    __half* __restrict__ yn, float* __restrict__ zn)
{
    __shared__ float sWl[16 * OUT_NEXT];   // [k][o]
    __shared__ float sWr[16 * OUT_NEXT];
    __shared__ float sb[OUT_NEXT];
    for (int i = threadIdx.x; i < 16 * OUT_NEXT; i += 256) {
        int o = i / 16, k = i - o * 16;
        sWl[k * OUT_NEXT + o] = Wl[i];
        sWr[k * OUT_NEXT + o] = Wr[i];
    }
    if (threadIdx.x < OUT_NEXT) sb[threadIdx.x] = bias[threadIdx.x];
    __syncthreads();

    int lane = threadIdx.x & 7;
    int node = (blockIdx.x * 256 + threadIdx.x) >> 3;   // grid exact: NN*8 % 256 == 0

    int beg = __ldg(off + node);
    int end = __ldg(off + node + 1);

    const __half2* y2 = reinterpret_cast<const __half2*>(y);
    float2 mean = gather_mean_h2(csr, y2, beg, end, lane);

    float2 zz = *reinterpret_cast<const float2*>(z + (size_t)node * 16 + 2 * lane);
    float v0 = elu_f(mean.x + zz.x);
    float v1 = elu_f(mean.y + zz.y);

    if (OUT_NEXT == 16) {
        int o0 = 2 * lane, o1 = 2 * lane + 1;
        float aY0 = 0.f, aY1 = 0.f, aZ0 = sb[o0], aZ1 = sb[o1];
#pragma unroll
        for (int k = 0; k < 8; k++) {
            float h0 = __shfl_sync(0xffffffffu, v0, k, 8);   // feature 2k
            float h1 = __shfl_sync(0xffffffffu, v1, k, 8);   // feature 2k+1
            aY0 = fmaf(h0, sWl[(2 * k) * 16 + o0], aY0);
            aY0 = fmaf(h1, sWl[(2 * k + 1) * 16 + o0], aY0);
            aY1 = fmaf(h0, sWl[(2 * k) * 16 + o1], aY1);
            aY1 = fmaf(h1, sWl[(2 * k + 1) * 16 + o1], aY1);
            aZ0 = fmaf(h0, sWr[(2 * k) * 16 + o0], aZ0);
            aZ0 = fmaf(h1, sWr[(2 * k + 1) * 16 + o0], aZ0);
            aZ1 = fmaf(h0, sWr[(2 * k) * 16 + o1], aZ1);
            aZ1 = fmaf(h1, sWr[(2 * k + 1) * 16 + o1], aZ1);
        }
        reinterpret_cast<__half2*>(yn)[(size_t)node * 8 + lane] =
            __floats2half2_rn(aY0, aY1);
        *reinterpret_cast<float2*>(zn + (size_t)node * 16 + 2 * lane) =
            make_float2(aZ0, aZ1);
    } else {   // OUT_NEXT == 8: one output per lane
        int o = lane;
        float aY = 0.f, aZ = sb[o];
#pragma unroll
        for (int k = 0; k < 8; k++) {
            float h0 = __shfl_sync(0xffffffffu, v0, k, 8);
            float h1 = __shfl_sync(0xffffffffu, v1, k, 8);
            aY = fmaf(h0, sWl[(2 * k) * 8 + o], aY);
            aY = fmaf(h1, sWl[(2 * k + 1) * 8 + o], aY);
            aZ = fmaf(h0, sWr[(2 * k) * 8 + o], aZ);
            aZ = fmaf(h1, sWr[(2 * k + 1) * 8 + o], aZ);
        }
        yn[(size_t)node * 8 + o] = __float2half_rn(aY);
        zn[(size_t)node * 8 + o] = aZ;
    }
}

// ---------------------------------------------------------------------------
// Final aggregate (width 8, scalar half lanes) + ELU + log_softmax (R9-proven).
// ---------------------------------------------------------------------------
__global__ void __launch_bounds__(256) agg_final_kernel(
    const int* __restrict__ off, const int* __restrict__ csr,
    const __half* __restrict__ y, const float* __restrict__ z,
    float* __restrict__ out)
{
    int lane = threadIdx.x & 7;
    int node = (blockIdx.x * 256 + threadIdx.x) >> 3;   // grid exact

    int beg = __ldg(off + node);
    int end = __ldg(off + node + 1);

    float acc = 0.0f;
    int i = beg;
    int a0 = 0, a1 = 0, a2 = 0, a3 = 0;
    bool have = (i + 4 <= end);
    if (have) {
        a0 = __ldg(csr + i + 0);
        a1 = __ldg(csr + i + 1);
        a2 = __ldg(csr + i + 2);
        a3 = __ldg(csr + i + 3);
    }
    for (; i + 8 <= end; i += 4) {
        int b0 = __ldg(csr + i + 4);
        int b1 = __ldg(csr + i + 5);
        int b2 = __ldg(csr + i + 6);
        int b3 = __ldg(csr + i + 7);
        float v0 = __half2float(__ldg(y + (size_t)a0 * 8 + lane));
        float v1 = __half2float(__ldg(y + (size_t)a1 * 8 + lane));
        float v2 = __half2float(__ldg(y + (size_t)a2 * 8 + lane));
        float v3 = __half2float(__ldg(y + (size_t)a3 * 8 + lane));
        acc += (v0 + v1) + (v2 + v3);
        a0 = b0; a1 = b1; a2 = b2; a3 = b3;
    }
    if (have) {
        float v0 = __half2float(__ldg(y + (size_t)a0 * 8 + lane));
        float v1 = __half2float(__ldg(y + (size_t)a1 * 8 + lane));
        float v2 = __half2float(__ldg(y + (size_t)a2 * 8 + lane));
        float v3 = __half2float(__ldg(y + (size_t)a3 * 8 + lane));
        acc += (v0 + v1) + (v2 + v3);
        i += 4;
    }
    for (; i < end; i++)
        acc += __half2float(__ldg(y + (size_t)__ldg(csr + i) * 8 + lane));

    float inv = 1.0f / fmaxf((float)(end - beg), 1.0f);
    float v = elu_f(fmaf(acc, inv, __ldg(z + (size_t)node * 8 + lane)));

    float m = v;
#pragma unroll
    for (int o = 4; o >= 1; o >>= 1)
        m = fmaxf(m, __shfl_xor_sync(0xffffffff, m, o, 8));
    float ex = expf(v - m);
    float s = ex;
#pragma unroll
    for (int o = 4; o >= 1; o >>= 1)
        s += __shfl_xor_sync(0xffffffff, s, o, 8);
    v = v - m - logf(s);

    out[(size_t)node * 8 + lane] = v;
}

// ---------------------------------------------------------------------------
extern "C" void kernel_launch(void* const* d_in, const int* in_sizes, int n_in,
                              void* d_out, int out_size)
{
    (void)in_sizes; (void)n_in; (void)out_size;

    const float* x   = (const float*)d_in[0];
    const int*   ei  = (const int*)d_in[1];   // int32 (JAX x64-disabled)
    const float* W1l = (const float*)d_in[2];
    const float* W1r = (const float*)d_in[3];
    const float* b1  = (const float*)d_in[4];
    const float* W2l = (const float*)d_in[5];
    const float* W2r = (const float*)d_in[6];
    const float* b2  = (const float*)d_in[7];
    const float* W3l = (const float*)d_in[8];
    const float* W3r = (const float*)d_in[9];
    const float* b3  = (const float*)d_in[10];
    float* out = (float*)d_out;

    const int* src = ei;
    const int* dst = ei + NE;

    __half *pyA, *pyB, *pyC;
    float *pzA, *pzB, *pzC;
    int *pcnt, *poff, *pcur, *pcsr;
    unsigned long long* pstate;
    cudaGetSymbolAddress((void**)&pyA,    g_yA);
    cudaGetSymbolAddress((void**)&pyB,    g_yB);
    cudaGetSymbolAddress((void**)&pyC,    g_yC);
    cudaGetSymbolAddress((void**)&pzA,    g_zA);
    cudaGetSymbolAddress((void**)&pzB,    g_zB);
    cudaGetSymbolAddress((void**)&pzC,    g_zC);
    cudaGetSymbolAddress((void**)&pcnt,   g_cnt);
    cudaGetSymbolAddress((void**)&poff,   g_off);
    cudaGetSymbolAddress((void**)&pcur,   g_cur);
    cudaGetSymbolAddress((void**)&pcsr,   g_csr);
    cudaGetSymbolAddress((void**)&pstate, g_state);

    const int nbN = (NN + 255) / 256;
    const int nbE = (NE + 255) / 256;

    // Fork: transform1 (independent of CSR build) on a side stream.
    cudaStream_t s2;
    cudaStreamCreateWithFlags(&s2, cudaStreamNonBlocking);
    cudaEvent_t evFork, evT1;
    cudaEventCreateWithFlags(&evFork, cudaEventDisableTiming);
    cudaEventCreateWithFlags(&evT1,   cudaEventDisableTiming);

    cudaEventRecord(evFork, 0);
    cudaStreamWaitEvent(s2, evFork, 0);
    transform2_kernel<48, 16><<<dim3(nbN, 2), 256, 0, s2>>>(x, W1l, W1r, b1, pyA, pzA);
    cudaEventRecord(evT1, s2);

    // ---- CSR build on the main stream (R9-proven) ----
    cudaMemsetAsync(pcnt, 0, NN * sizeof(int));
    cudaMemsetAsync(pstate, 0, NCHUNK * sizeof(unsigned long long));
    hist_kernel<<<nbE, 256>>>(dst, pcnt);
    scan_onepass_kernel<<<NCHUNK, 256>>>(pcnt, poff, pcur);
    place_kernel<<<nbE, 256>>>(src, dst, pcur, pcsr);

    cudaStreamWaitEvent(0, evT1, 0);     // join transform1

    // ---- Layer 1 agg + layer 2 transform: -> yB,zB (16) ----
    agg_xform_kernel<16><<<NN * 8 / 256, 256>>>(poff, pcsr, pyA, pzA,
                                                W2l, W2r, b2, pyB, pzB);
    // ---- Layer 2 agg + layer 3 transform: -> yC,zC (8) ----
    agg_xform_kernel<8><<<NN * 8 / 256, 256>>>(poff, pcsr, pyB, pzB,
                                               W3l, W3r, b3, pyC, pzC);
    // ---- Layer 3 agg + log_softmax ----
    agg_final_kernel<<<NN * 8 / 256, 256>>>(poff, pcsr, pyC, pzC, out);
}